// round 10
// baseline (speedup 1.0000x reference)
#include <cuda_runtime.h>

// 2-layer LSTM (B=2048, T=1024, I=6, H=38) + projection (C=8), fp32.
// grid=128 persistent blocks, 16 batches/block, 480 threads = 3 warp groups.
//   A  (t0..159):   layer 0 @ step t       (K = 6 x + 40 h0)
//   B1 (t160..319): layer 1 @ step t-1, partial over h0 half (40 k) -> SMEM
//   B2 (t320..479): layer 1 @ step t-1, partial over h1 half (40 k) + bias,
//                   combines with B1's partial after bar1, activations, h1.
// Thread = (px 0..3, q 0..39), 4 batches. Per k: 1 LDS.128 W + 1 LDS.128 h,
// 4 reg splats (ALU), 8 fma.rn.f32x2 = 16 MACs / 4 L1-cycles.

namespace {
constexpr int Bsz = 2048, Tt = 1024, NI = 6, H = 38, HP = 40, Cc = 8;
constexpr int BT = 16;             // batches per block
constexpr int GRP = 4 * HP;        // 160 threads per group
constexpr int NTHR = 3 * GRP;      // 480
constexpr int WAN = (NI + HP) * HP * 4;   // 7360 floats
constexpr int WBN = (HP + HP) * HP * 4;   // 12800 floats
constexpr int S0ROWS = NI + 2 * HP;   // x rows + h0 double-buffer (A-private)
constexpr int S1ROWS = 4 * HP;        // h0 dbl-buf + h1 dbl-buf (B side)
constexpr int S0N = S0ROWS * BT;      // 1376
constexpr int S1N = S1ROWS * BT;      // 2560
constexpr int PARTN = GRP * 16;       // B1 partial gate sums: 2560 floats
constexpr int SMEM_FLOATS = WAN + WBN + S0N + S1N + PARTN;  // 26656 -> 106624 B
}

typedef unsigned long long ull;

__device__ __forceinline__ ull pk2(float a, float b) {
    ull r; asm("mov.b64 %0, {%1, %2};" : "=l"(r) : "f"(a), "f"(b)); return r;
}
__device__ __forceinline__ ull splat(float v) {
    ull r; asm("mov.b64 %0, {%1, %1};" : "=l"(r) : "f"(v)); return r;
}
__device__ __forceinline__ void fma2(ull &d, ull a, ull b) {
    asm("fma.rn.f32x2 %0, %1, %2, %0;" : "+l"(d) : "l"(a), "l"(b));
}
__device__ __forceinline__ void add2(ull &d, ull a) {
    asm("add.rn.f32x2 %0, %0, %1;" : "+l"(d) : "l"(a));
}
__device__ __forceinline__ void unpk2(ull v, float &a, float &b) {
    asm("mov.b64 {%0, %1}, %2;" : "=f"(a), "=f"(b) : "l"(v));
}
__device__ __forceinline__ float sigm(float x) {
    return __fdividef(1.0f, 1.0f + __expf(-x));
}
__device__ __forceinline__ float tanh_(float x) {
    return __fdividef(2.0f, 1.0f + __expf(-2.0f * x)) - 1.0f;
}

// 40-k gate-accumulation over one state buffer half
__device__ __forceinline__ void acc40(const float* __restrict__ hbase,
                                      const float* __restrict__ wbase,
                                      ull aif[4], ull ago[4]) {
    #pragma unroll
    for (int k = 0; k < HP; ++k) {
        float4 hv = *(const float4*)(hbase + k * BT);
        ulonglong2 w = *(const ulonglong2*)(wbase + k * (4 * HP));
        ull h0s = splat(hv.x), h1s = splat(hv.y), h2s = splat(hv.z), h3s = splat(hv.w);
        fma2(aif[0], h0s, w.x); fma2(ago[0], h0s, w.y);
        fma2(aif[1], h1s, w.x); fma2(ago[1], h1s, w.y);
        fma2(aif[2], h2s, w.x); fma2(ago[2], h2s, w.y);
        fma2(aif[3], h3s, w.x); fma2(ago[3], h3s, w.y);
    }
}

__global__ void __launch_bounds__(NTHR, 1) lstm_kernel(
    const float* __restrict__ x,    const float* __restrict__ Wih0,
    const float* __restrict__ Whh0, const float* __restrict__ b0,
    const float* __restrict__ Wih1, const float* __restrict__ Whh1,
    const float* __restrict__ b1,   const float* __restrict__ Wc,
    const float* __restrict__ bc,   float* __restrict__ out)
{
    extern __shared__ float sm[];
    float* WA   = sm;              // [k][q][4]={wi,wf,wg,wo}, k: 0..5 x, 6..45 h0
    float* WB   = WA + WAN;        // [k][q][4], k: 0..39 h0-half, 40..79 h1-half
    float* s0   = WB + WBN;        // A-private: x rows + h0 dbl-buf
    float* s1   = s0 + S0N;        // h0 dbl-buf (A->B1) + h1 dbl-buf (B2)
    float* part = s1 + S1N;        // B1 partial accumulators [lt][16]

    const int tid = threadIdx.x;
    const int grp = tid / GRP;           // 0=A, 1=B1, 2=B2
    const int lt  = tid - grp * GRP;
    const int px  = lt & 3;
    const int q   = lt >> 2;
    const int bb0 = blockIdx.x * BT + 4 * px;

    // ---- stage weights (zero-padded) ----
    for (int idx = tid; idx < WAN; idx += NTHR) {
        int g = idx & 3, qq = (idx >> 2) % HP, k = idx / (4 * HP);
        float v = 0.0f;
        if (qq < H) {
            int row = g * H + qq;
            if (k < NI)          v = Wih0[row * NI + k];
            else { int kk = k - NI; if (kk < H) v = Whh0[row * H + kk]; }
        }
        WA[idx] = v;
    }
    for (int idx = tid; idx < WBN; idx += NTHR) {
        int g = idx & 3, qq = (idx >> 2) % HP, k = idx / (4 * HP);
        float v = 0.0f;
        if (qq < H) {
            int row = g * H + qq;
            if (k < HP) { if (k < H) v = Wih1[row * H + k]; }
            else        { int kk = k - HP; if (kk < H) v = Whh1[row * H + kk]; }
        }
        WB[idx] = v;
    }
    for (int idx = tid; idx < S0N + S1N + PARTN; idx += NTHR) s0[idx] = 0.0f;

    // ---- per-thread packed biases ----
    ull bif, bgo;
    if (grp == 0 && q < H) {                       // A: layer-0 bias
        bif = pk2(b0[q], b0[H + q]); bgo = pk2(b0[2 * H + q], b0[3 * H + q]);
    } else if (grp == 2 && q < H) {                // B2: layer-1 bias
        bif = pk2(b1[q], b1[H + q]); bgo = pk2(b1[2 * H + q], b1[3 * H + q]);
    } else {                                       // B1 and padded units: zero
        bif = bgo = pk2(0.0f, 0.0f);
    }

    // ---- x(0) into s0.x rows ----
    if (grp == 0 && q < NI) {
        float4 xv;
        xv.x = x[(size_t)(bb0 + 0) * Tt * NI + q];
        xv.y = x[(size_t)(bb0 + 1) * Tt * NI + q];
        xv.z = x[(size_t)(bb0 + 2) * Tt * NI + q];
        xv.w = x[(size_t)(bb0 + 3) * Tt * NI + q];
        *(float4*)(s0 + q * BT + 4 * px) = xv;
    }
    __syncthreads();

    float cst[4] = {0.f, 0.f, 0.f, 0.f};    // A: layer-0 c; B2: layer-1 c
    const int hoff = 4 * px;
    ull* pp = (ull*)part + (size_t)lt * 8;   // B1/B2 exchange slot

    for (int it = 0; it <= Tt; ++it) {
        const int p  = it & 1;
        const int nb = p ^ 1;
        float hr[4];
        ull aif[4], ago[4];

        // A: x_{t+1} prefetch (in flight during compute)
        float xn0 = 0.f, xn1 = 0.f, xn2 = 0.f, xn3 = 0.f;
        if (grp == 0 && q < NI && it + 1 < Tt) {
            size_t o = (size_t)(it + 1) * NI + q;
            xn0 = x[(size_t)(bb0 + 0) * Tt * NI + o];
            xn1 = x[(size_t)(bb0 + 1) * Tt * NI + o];
            xn2 = x[(size_t)(bb0 + 2) * Tt * NI + o];
            xn3 = x[(size_t)(bb0 + 3) * Tt * NI + o];
        }

        // ---------------- compute phase ----------------
        if (grp == 0) {
            if (it < Tt) {
                #pragma unroll
                for (int j = 0; j < 4; ++j) { aif[j] = bif; ago[j] = bgo; }
                const float* wa = WA + 4 * q;
                const float* hx = s0 + hoff;
                #pragma unroll
                for (int k = 0; k < NI; ++k) {       // x part (6 k)
                    float4 hv = *(const float4*)(hx + k * BT);
                    ulonglong2 w = *(const ulonglong2*)(wa + k * (4 * HP));
                    ull h0s = splat(hv.x), h1s = splat(hv.y), h2s = splat(hv.z), h3s = splat(hv.w);
                    fma2(aif[0], h0s, w.x); fma2(ago[0], h0s, w.y);
                    fma2(aif[1], h1s, w.x); fma2(ago[1], h1s, w.y);
                    fma2(aif[2], h2s, w.x); fma2(ago[2], h2s, w.y);
                    fma2(aif[3], h3s, w.x); fma2(ago[3], h3s, w.y);
                }
                acc40(s0 + (NI + p * HP) * BT + hoff, WA + NI * (4 * HP) + 4 * q, aif, ago);
                #pragma unroll
                for (int j = 0; j < 4; ++j) {
                    float gi, gf, gg, go;
                    unpk2(aif[j], gi, gf); unpk2(ago[j], gg, go);
                    float i = sigm(gi), f = sigm(gf), g = tanh_(gg), o = sigm(go);
                    cst[j] = f * cst[j] + i * g;
                    hr[j] = o * tanh_(cst[j]);
                }
            }
        } else if (grp == 1) {
            if (it >= 1) {
                #pragma unroll
                for (int j = 0; j < 4; ++j) { aif[j] = bif; ago[j] = bgo; }  // zeros
                acc40(s1 + p * HP * BT + hoff, WB + 4 * q, aif, ago);
                ulonglong2 v01, v23, w01, w23;
                v01.x = aif[0]; v01.y = aif[1]; v23.x = aif[2]; v23.y = aif[3];
                w01.x = ago[0]; w01.y = ago[1]; w23.x = ago[2]; w23.y = ago[3];
                *(ulonglong2*)(pp + 0) = v01; *(ulonglong2*)(pp + 2) = v23;
                *(ulonglong2*)(pp + 4) = w01; *(ulonglong2*)(pp + 6) = w23;
            }
        } else {
            if (it >= 1) {
                #pragma unroll
                for (int j = 0; j < 4; ++j) { aif[j] = bif; ago[j] = bgo; }  // layer-1 bias
                acc40(s1 + (2 + p) * HP * BT + hoff, WB + HP * (4 * HP) + 4 * q, aif, ago);
            }
        }

        __syncthreads();   // bar1: reads of p done; B1 partials visible

        // ---------------- combine / write phase ----------------
        if (grp == 0) {
            if (it < Tt) {
                float4 hv4 = make_float4(hr[0], hr[1], hr[2], hr[3]);
                *(float4*)(s0 + (NI + nb * HP + q) * BT + hoff) = hv4;  // next A step
                *(float4*)(s1 + (nb * HP + q) * BT + hoff) = hv4;       // B1 @ it+1
                if (q < NI && it + 1 < Tt)
                    *(float4*)(s0 + q * BT + hoff) = make_float4(xn0, xn1, xn2, xn3);
            }
        } else if (grp == 2) {
            if (it >= 1) {
                ulonglong2 v01 = *(const ulonglong2*)(pp + 0);
                ulonglong2 v23 = *(const ulonglong2*)(pp + 2);
                ulonglong2 w01 = *(const ulonglong2*)(pp + 4);
                ulonglong2 w23 = *(const ulonglong2*)(pp + 6);
                add2(aif[0], v01.x); add2(aif[1], v01.y);
                add2(aif[2], v23.x); add2(aif[3], v23.y);
                add2(ago[0], w01.x); add2(ago[1], w01.y);
                add2(ago[2], w23.x); add2(ago[3], w23.y);
                #pragma unroll
                for (int j = 0; j < 4; ++j) {
                    float gi, gf, gg, go;
                    unpk2(aif[j], gi, gf); unpk2(ago[j], gg, go);
                    float i = sigm(gi), f = sigm(gf), g = tanh_(gg), o = sigm(go);
                    cst[j] = f * cst[j] + i * g;
                    hr[j] = o * tanh_(cst[j]);
                }
                *(float4*)(s1 + ((2 + nb) * HP + q) * BT + hoff) =
                    make_float4(hr[0], hr[1], hr[2], hr[3]);
            }
        }

        __syncthreads();   // bar2: nb-buffer writes visible
    }

    // ---- final projection from h1(T-1) in buffer (Tt+1)&1 ----
    if (grp == 0 && q < Cc) {
        const int bufL = (Tt + 1) & 1;
        const float* hl = s1 + (2 + bufL) * HP * BT + hoff;
        float a0 = bc[q], a1 = a0, a2 = a0, a3 = a0;
        #pragma unroll
        for (int k = 0; k < H; ++k) {
            float w = Wc[q * H + k];
            float4 hv = *(const float4*)(hl + k * BT);
            a0 += w * hv.x; a1 += w * hv.y; a2 += w * hv.z; a3 += w * hv.w;
        }
        out[(size_t)(bb0 + 0) * Cc + q] = a0;
        out[(size_t)(bb0 + 1) * Cc + q] = a1;
        out[(size_t)(bb0 + 2) * Cc + q] = a2;
        out[(size_t)(bb0 + 3) * Cc + q] = a3;
    }
}

extern "C" void kernel_launch(void* const* d_in, const int* in_sizes, int n_in,
                              void* d_out, int out_size) {
    const float* x    = (const float*)d_in[0];
    const float* Wih0 = (const float*)d_in[1];
    const float* Whh0 = (const float*)d_in[2];
    const float* b0   = (const float*)d_in[3];
    const float* Wih1 = (const float*)d_in[4];
    const float* Whh1 = (const float*)d_in[5];
    const float* b1   = (const float*)d_in[6];
    const float* Wc   = (const float*)d_in[7];
    const float* bc   = (const float*)d_in[8];

    const int smem_bytes = SMEM_FLOATS * (int)sizeof(float);
    cudaFuncSetAttribute(lstm_kernel, cudaFuncAttributeMaxDynamicSharedMemorySize, smem_bytes);
    lstm_kernel<<<Bsz / BT, NTHR, smem_bytes>>>(
        x, Wih0, Whh0, b0, Wih1, Whh1, b1, Wc, bc, (float*)d_out);
}

// round 11
// speedup vs baseline: 1.0911x; 1.0911x over previous
#include <cuda_runtime.h>

// 2-layer LSTM (B=2048, T=1024, I=6, H=38) + projection (C=8), fp32.
// grid=128 persistent blocks, 16 batches/block, 320 threads, ONE barrier/step.
//   group A (0..159):   layer 0 @ step t
//   group B (160..319): layer 1 @ step t-1
// All buffers (x rows, h0, h1) double-buffered by iteration parity:
// reads hit parity p, writes hit parity nb => single __syncthreads per step.
// B reads h0 from the SAME buffer rows A reads (broadcast-friendly).
// Thread = (px 0..3, q 0..39), 4 batches. Per k: 1 LDS.128 W + 1 LDS.128 h,
// 4 reg splats (ALU) + 8 fma.rn.f32x2 = 16 MACs / 4 L1-cycles.

namespace {
constexpr int Bsz = 2048, Tt = 1024, NI = 6, H = 38, HP = 40, Cc = 8;
constexpr int BT = 16;             // batches per block
constexpr int GRP = 4 * HP;        // 160 threads per group
constexpr int NTHR = 2 * GRP;      // 320
constexpr int WAN = (NI + HP) * HP * 4;   // 7360 floats
constexpr int WBN = (HP + HP) * HP * 4;   // 12800 floats
// s0 rows: x double-buffer [0..2*NI), h0 double-buffer [2*NI..2*NI+2*HP)
// s1 rows: h1 double-buffer [0..2*HP)
constexpr int S0ROWS = 2 * NI + 2 * HP;   // 92
constexpr int S1ROWS = 2 * HP;            // 80
constexpr int S0N = S0ROWS * BT;          // 1472
constexpr int S1N = S1ROWS * BT;          // 1280
constexpr int SMEM_FLOATS = WAN + WBN + S0N + S1N;  // 22912 -> 91648 B
}

typedef unsigned long long ull;

__device__ __forceinline__ ull pk2(float a, float b) {
    ull r; asm("mov.b64 %0, {%1, %2};" : "=l"(r) : "f"(a), "f"(b)); return r;
}
__device__ __forceinline__ ull splat(float v) {
    ull r; asm("mov.b64 %0, {%1, %1};" : "=l"(r) : "f"(v)); return r;
}
__device__ __forceinline__ void fma2(ull &d, ull a, ull b) {
    asm("fma.rn.f32x2 %0, %1, %2, %0;" : "+l"(d) : "l"(a), "l"(b));
}
__device__ __forceinline__ void unpk2(ull v, float &a, float &b) {
    asm("mov.b64 {%0, %1}, %2;" : "=f"(a), "=f"(b) : "l"(v));
}
__device__ __forceinline__ float sigm(float x) {
    return __fdividef(1.0f, 1.0f + __expf(-x));
}
__device__ __forceinline__ float tanh_(float x) {
    return __fdividef(2.0f, 1.0f + __expf(-2.0f * x)) - 1.0f;
}

// 40-k gate accumulation over one state buffer half
__device__ __forceinline__ void acc40(const float* __restrict__ hbase,
                                      const float* __restrict__ wbase,
                                      ull aif[4], ull ago[4]) {
    #pragma unroll
    for (int k = 0; k < HP; ++k) {
        float4 hv = *(const float4*)(hbase + k * BT);
        ulonglong2 w = *(const ulonglong2*)(wbase + k * (4 * HP));
        ull h0s = splat(hv.x), h1s = splat(hv.y), h2s = splat(hv.z), h3s = splat(hv.w);
        fma2(aif[0], h0s, w.x); fma2(ago[0], h0s, w.y);
        fma2(aif[1], h1s, w.x); fma2(ago[1], h1s, w.y);
        fma2(aif[2], h2s, w.x); fma2(ago[2], h2s, w.y);
        fma2(aif[3], h3s, w.x); fma2(ago[3], h3s, w.y);
    }
}

__global__ void __launch_bounds__(NTHR, 1) lstm_kernel(
    const float* __restrict__ x,    const float* __restrict__ Wih0,
    const float* __restrict__ Whh0, const float* __restrict__ b0,
    const float* __restrict__ Wih1, const float* __restrict__ Whh1,
    const float* __restrict__ b1,   const float* __restrict__ Wc,
    const float* __restrict__ bc,   float* __restrict__ out)
{
    extern __shared__ float sm[];
    float* WA = sm;             // [k][q][4]={wi,wf,wg,wo}, k: 0..5 x, 6..45 h0
    float* WB = WA + WAN;       // [k][q][4],               k: 0..39 h0, 40..79 h1
    float* s0 = WB + WBN;       // x dbl-buf rows + h0 dbl-buf rows
    float* s1 = s0 + S0N;       // h1 dbl-buf rows

    const int tid = threadIdx.x;
    const int grp = tid >= GRP;          // 0 = layer0 (A), 1 = layer1 (B)
    const int lt  = tid - grp * GRP;
    const int px  = lt & 3;
    const int q   = lt >> 2;
    const int bb0 = blockIdx.x * BT + 4 * px;

    // ---- stage weights (zero-padded units / k rows) ----
    for (int idx = tid; idx < WAN; idx += NTHR) {
        int g = idx & 3, qq = (idx >> 2) % HP, k = idx / (4 * HP);
        float v = 0.0f;
        if (qq < H) {
            int row = g * H + qq;
            if (k < NI)          v = Wih0[row * NI + k];
            else { int kk = k - NI; if (kk < H) v = Whh0[row * H + kk]; }
        }
        WA[idx] = v;
    }
    for (int idx = tid; idx < WBN; idx += NTHR) {
        int g = idx & 3, qq = (idx >> 2) % HP, k = idx / (4 * HP);
        float v = 0.0f;
        if (qq < H) {
            int row = g * H + qq;
            if (k < HP) { if (k < H) v = Wih1[row * H + k]; }
            else        { int kk = k - HP; if (kk < H) v = Whh1[row * H + kk]; }
        }
        WB[idx] = v;
    }
    for (int idx = tid; idx < S0N; idx += NTHR) s0[idx] = 0.0f;
    for (int idx = tid; idx < S1N; idx += NTHR) s1[idx] = 0.0f;

    // ---- per-thread packed biases for this thread's layer ----
    ull bif, bgo;
    if (q < H) {
        const float* b = grp ? b1 : b0;
        bif = pk2(b[q], b[H + q]);
        bgo = pk2(b[2 * H + q], b[3 * H + q]);
    } else {
        bif = bgo = pk2(0.0f, 0.0f);
    }

    // ---- x(0) into x buffer 0 ----
    if (grp == 0 && q < NI) {
        float4 xv;
        xv.x = x[(size_t)(bb0 + 0) * Tt * NI + q];
        xv.y = x[(size_t)(bb0 + 1) * Tt * NI + q];
        xv.z = x[(size_t)(bb0 + 2) * Tt * NI + q];
        xv.w = x[(size_t)(bb0 + 3) * Tt * NI + q];
        *(float4*)(s0 + q * BT + 4 * px) = xv;
    }
    __syncthreads();

    float cst[4] = {0.f, 0.f, 0.f, 0.f};   // A: layer-0 c; B: layer-1 c
    const int hoff = 4 * px;

    // iteration it: A computes layer0 step it (it < Tt);
    //               B computes layer1 step it-1 (it >= 1).
    // reads: parity-p buffers; writes: parity-nb buffers; ONE barrier at end.
    for (int it = 0; it <= Tt; ++it) {
        const int p  = it & 1;
        const int nb = p ^ 1;

        if (grp == 0) {
            if (it < Tt) {
                // x_{t+1} prefetch, in flight during compute
                float xn0 = 0.f, xn1 = 0.f, xn2 = 0.f, xn3 = 0.f;
                if (q < NI && it + 1 < Tt) {
                    size_t o = (size_t)(it + 1) * NI + q;
                    xn0 = x[(size_t)(bb0 + 0) * Tt * NI + o];
                    xn1 = x[(size_t)(bb0 + 1) * Tt * NI + o];
                    xn2 = x[(size_t)(bb0 + 2) * Tt * NI + o];
                    xn3 = x[(size_t)(bb0 + 3) * Tt * NI + o];
                }
                ull aif[4], ago[4];
                #pragma unroll
                for (int j = 0; j < 4; ++j) { aif[j] = bif; ago[j] = bgo; }
                const float* wa = WA + 4 * q;
                const float* hx = s0 + p * NI * BT + hoff;      // x buf p
                #pragma unroll
                for (int k = 0; k < NI; ++k) {
                    float4 hv = *(const float4*)(hx + k * BT);
                    ulonglong2 w = *(const ulonglong2*)(wa + k * (4 * HP));
                    ull h0s = splat(hv.x), h1s = splat(hv.y), h2s = splat(hv.z), h3s = splat(hv.w);
                    fma2(aif[0], h0s, w.x); fma2(ago[0], h0s, w.y);
                    fma2(aif[1], h1s, w.x); fma2(ago[1], h1s, w.y);
                    fma2(aif[2], h2s, w.x); fma2(ago[2], h2s, w.y);
                    fma2(aif[3], h3s, w.x); fma2(ago[3], h3s, w.y);
                }
                acc40(s0 + (2 * NI + p * HP) * BT + hoff,       // h0 buf p
                      WA + NI * (4 * HP) + 4 * q, aif, ago);
                float hr[4];
                #pragma unroll
                for (int j = 0; j < 4; ++j) {
                    float gi, gf, gg, go;
                    unpk2(aif[j], gi, gf); unpk2(ago[j], gg, go);
                    float i = sigm(gi), f = sigm(gf), g = tanh_(gg), o = sigm(go);
                    cst[j] = f * cst[j] + i * g;
                    hr[j] = o * tanh_(cst[j]);
                }
                // writes -> nb buffers only
                *(float4*)(s0 + (2 * NI + nb * HP + q) * BT + hoff) =
                    make_float4(hr[0], hr[1], hr[2], hr[3]);
                if (q < NI && it + 1 < Tt)
                    *(float4*)(s0 + (nb * NI + q) * BT + hoff) =
                        make_float4(xn0, xn1, xn2, xn3);
            }
        } else {
            if (it >= 1) {
                ull aif[4], ago[4];
                #pragma unroll
                for (int j = 0; j < 4; ++j) { aif[j] = bif; ago[j] = bgo; }
                // h0(it-1) lives in s0 h0 buf p (same rows A reads)
                acc40(s0 + (2 * NI + p * HP) * BT + hoff, WB + 4 * q, aif, ago);
                // h1(it-2) in s1 buf p
                acc40(s1 + p * HP * BT + hoff, WB + HP * (4 * HP) + 4 * q, aif, ago);
                float hr[4];
                #pragma unroll
                for (int j = 0; j < 4; ++j) {
                    float gi, gf, gg, go;
                    unpk2(aif[j], gi, gf); unpk2(ago[j], gg, go);
                    float i = sigm(gi), f = sigm(gf), g = tanh_(gg), o = sigm(go);
                    cst[j] = f * cst[j] + i * g;
                    hr[j] = o * tanh_(cst[j]);
                }
                *(float4*)(s1 + (nb * HP + q) * BT + hoff) =
                    make_float4(hr[0], hr[1], hr[2], hr[3]);
            }
        }

        __syncthreads();   // single barrier: nb writes visible, p reads done
    }

    // ---- final projection from h1(Tt-1), written at it=Tt into buf (Tt+1)&1 ----
    if (grp == 0 && q < Cc) {
        const int bufL = (Tt + 1) & 1;
        const float* hl = s1 + bufL * HP * BT + hoff;
        float a0 = bc[q], a1 = a0, a2 = a0, a3 = a0;
        #pragma unroll
        for (int k = 0; k < H; ++k) {
            float w = Wc[q * H + k];
            float4 hv = *(const float4*)(hl + k * BT);
            a0 += w * hv.x; a1 += w * hv.y; a2 += w * hv.z; a3 += w * hv.w;
        }
        out[(size_t)(bb0 + 0) * Cc + q] = a0;
        out[(size_t)(bb0 + 1) * Cc + q] = a1;
        out[(size_t)(bb0 + 2) * Cc + q] = a2;
        out[(size_t)(bb0 + 3) * Cc + q] = a3;
    }
}

extern "C" void kernel_launch(void* const* d_in, const int* in_sizes, int n_in,
                              void* d_out, int out_size) {
    const float* x    = (const float*)d_in[0];
    const float* Wih0 = (const float*)d_in[1];
    const float* Whh0 = (const float*)d_in[2];
    const float* b0   = (const float*)d_in[3];
    const float* Wih1 = (const float*)d_in[4];
    const float* Whh1 = (const float*)d_in[5];
    const float* b1   = (const float*)d_in[6];
    const float* Wc   = (const float*)d_in[7];
    const float* bc   = (const float*)d_in[8];

    const int smem_bytes = SMEM_FLOATS * (int)sizeof(float);
    cudaFuncSetAttribute(lstm_kernel, cudaFuncAttributeMaxDynamicSharedMemorySize, smem_bytes);
    lstm_kernel<<<Bsz / BT, NTHR, smem_bytes>>>(
        x, Wih0, Whh0, b0, Wih1, Whh1, b1, Wc, bc, (float*)d_out);
}